// round 17
// baseline (speedup 1.0000x reference)
#include <cuda_runtime.h>
#include <cstdint>
#include <math.h>

// ---------------------------------------------------------------------------
// 2-layer LSTM (B=64, T=2048, D=64, H=512) + linear head + log_softmax.
//
// R17: fused-input, single-sync round with double-buffered partials.
// Round r (r = 0..T+1):
//   [warps 0-7: gates-L1 t=r-2 (gp1[(r-1)&1]) -> publish B[r-2]]
//   [warps 8-15: gates-L0 t=r-1 (gp0[(r-1)&1]) -> publish A[r-1]]
//   all: rec-L1 gemv (wait B[r-2]) ->
//        FUSED h1[r-1] gemv: one LDG feeds w1ff (L1 accs) AND w0 (L0 accs)
//        (wait A[r-1], buried behind rec) -> x-ff gemv ->
//        cstore gp1[r&1], gp0[r&1] -> ONE __syncthreads.
// Warp = (k-slice 0..3, row-half, batch-half): 4 gate-row pairs per lane-half,
// k-parity inner loop (1 coalesced LDG.64 + LDS.128 pairs shared across
// halves). Fusion removes the duplicate h1 read (-32% LDG); gates are
// balanced across all warps; 2 syncs -> 1.
// ---------------------------------------------------------------------------

namespace {
constexpr int B_   = 64;
constexpr int T_   = 2048;
constexpr int D_   = 64;
constexpr int H_   = 512;
constexpr int OUT_ = 10;
constexpr int NCTA = 128;
constexpr int NTHR = 512;                 // 16 warps
constexpr int ROWS = 16;                  // gate rows per layer per CTA
constexpr int K0   = H_ + D_;
constexpr int K1   = H_ + H_;
constexpr int GPW  = 4 * 8 * B_;          // u64 words per gp buffer (2048)

constexpr size_t OFF_W0  = 0;                                   // [576][16]
constexpr size_t OFF_W1  = OFF_W0 + (size_t)K0 * ROWS * 4;      //  36864
constexpr size_t OFF_GP0 = OFF_W1 + (size_t)K1 * ROWS * 4;      // 102400
constexpr size_t OFF_GP1 = OFF_GP0 + (size_t)2 * GPW * 8;       // 135168
constexpr size_t OFF_CST = OFF_GP1 + (size_t)2 * GPW * 8;       // 167936
constexpr size_t OFF_BIA = OFF_CST + 2048;                      // 169984
constexpr size_t SMEM_BYTES = OFF_BIA + 128;                    // 170112

constexpr int HV_STRIDE = 521;                  // head staging
constexpr size_t OFF_LG = (size_t)B_ * HV_STRIDE * 4;           // 133376
}

// Static device scratch (no runtime allocation).
__device__ float g_h1[(size_t)T_ * H_ * B_];   // layer0 h, [t][unit][b]
__device__ float g_h2[(size_t)T_ * H_ * B_];   // layer1 h, [t][unit][b]
__device__ float g_xT[(size_t)T_ * D_ * B_];   // x transposed, [t][k][b]
__device__ int   g_cntA[T_ + 1];               // h1[t] ready counters
__device__ int   g_cntB[T_ + 1];               // h2[t] ready counters

__device__ __forceinline__ void ffma2(uint64_t& acc, uint64_t a, uint64_t b) {
    asm("fma.rn.f32x2 %0, %1, %2, %0;" : "+l"(acc) : "l"(a), "l"(b));
}
__device__ __forceinline__ void addf2(uint64_t& acc, uint64_t a) {
    asm("add.rn.f32x2 %0, %0, %1;" : "+l"(acc) : "l"(a));
}
__device__ __forceinline__ uint64_t dup2(float x) {
    uint64_t r;
    asm("mov.b64 %0, {%1, %1};" : "=l"(r) : "f"(x));
    return r;
}
__device__ __forceinline__ int ld_acq(const int* p) {
    int v;
    asm volatile("ld.global.acquire.gpu.b32 %0, [%1];" : "=r"(v) : "l"(p));
    return v;
}
__device__ __forceinline__ void wait_warp(const int* p) {
    if ((threadIdx.x & 31) == 0) {
        while (ld_acq(p) < NCTA) {}
    }
    __syncwarp();
}
__device__ __forceinline__ float fast_sigmoid(float x) {
    return __fdividef(1.f, 1.f + __expf(-x));
}
__device__ __forceinline__ float fast_tanh(float x) {
    float a = fabsf(x);
    float t = __expf(-2.f * a);
    float r = __fdividef(1.f - t, 1.f + t);
    return copysignf(r, x);
}

// 4-pair k-parity GEMV: lane-half h handles rows k+h; pairs pq*2..pq*2+3.
__device__ __forceinline__ void gemv4p(uint64_t aA[4], uint64_t aB[4],
                                       const float* __restrict__ wsm,
                                       const float* __restrict__ in,
                                       int kb, int ke, int b2, int h, int pq) {
#pragma unroll 8
    for (int k = kb; k < ke; k += 2) {
        int kk = k + h;
        float2 v = *(const float2*)(in + (size_t)kk * B_ + b2);
        uint64_t x0 = dup2(v.x);
        uint64_t x1 = dup2(v.y);
        const ulonglong2* wv = (const ulonglong2*)(wsm + (size_t)kk * ROWS);
        ulonglong2 wA = wv[pq];
        ulonglong2 wB = wv[pq + 1];
        ffma2(aA[0], wA.x, x0); ffma2(aB[0], wA.x, x1);
        ffma2(aA[1], wA.y, x0); ffma2(aB[1], wA.y, x1);
        ffma2(aA[2], wB.x, x0); ffma2(aB[2], wB.x, x1);
        ffma2(aA[3], wB.y, x0); ffma2(aB[3], wB.y, x1);
    }
}

// Fused: ONE input load feeds two weight sets (w1ff -> L1 accs, w0 -> L0).
__device__ __forceinline__ void gemv4p_pair(uint64_t a1A[4], uint64_t a1B[4],
                                            uint64_t a0A[4], uint64_t a0B[4],
                                            const float* __restrict__ w1k,
                                            const float* __restrict__ w0k,
                                            const float* __restrict__ in,
                                            int kb, int ke, int b2, int h,
                                            int pq) {
#pragma unroll 4
    for (int k = kb; k < ke; k += 2) {
        int kk = k + h;
        float2 v = *(const float2*)(in + (size_t)kk * B_ + b2);
        uint64_t x0 = dup2(v.x);
        uint64_t x1 = dup2(v.y);
        {
            const ulonglong2* wv = (const ulonglong2*)(w1k + (size_t)kk * ROWS);
            ulonglong2 wA = wv[pq];
            ulonglong2 wB = wv[pq + 1];
            ffma2(a1A[0], wA.x, x0); ffma2(a1B[0], wA.x, x1);
            ffma2(a1A[1], wA.y, x0); ffma2(a1B[1], wA.y, x1);
            ffma2(a1A[2], wB.x, x0); ffma2(a1B[2], wB.x, x1);
            ffma2(a1A[3], wB.y, x0); ffma2(a1B[3], wB.y, x1);
        }
        {
            const ulonglong2* wv = (const ulonglong2*)(w0k + (size_t)kk * ROWS);
            ulonglong2 wA = wv[pq];
            ulonglong2 wB = wv[pq + 1];
            ffma2(a0A[0], wA.x, x0); ffma2(a0B[0], wA.x, x1);
            ffma2(a0A[1], wA.y, x0); ffma2(a0B[1], wA.y, x1);
            ffma2(a0A[2], wB.x, x0); ffma2(a0B[2], wB.x, x1);
            ffma2(a0A[3], wB.y, x0); ffma2(a0B[3], wB.y, x1);
        }
    }
}

// Combine k-parities (shfl 16) and store 4 pairs; lanes 0-15 write.
__device__ __forceinline__ void cstore4(uint64_t aA[4], uint64_t aB[4],
                                        uint64_t* __restrict__ gpb,
                                        int ks, int rh, int b2, int lane) {
#pragma unroll
    for (int p = 0; p < 4; ++p) {
        unsigned long long oA = __shfl_xor_sync(0xffffffffu,
                                                (unsigned long long)aA[p], 16);
        unsigned long long oB = __shfl_xor_sync(0xffffffffu,
                                                (unsigned long long)aB[p], 16);
        addf2(aA[p], (uint64_t)oA);
        addf2(aB[p], (uint64_t)oB);
    }
    if (lane < 16) {
#pragma unroll
        for (int p = 0; p < 4; ++p) {
            *(ulonglong2*)(gpb + (size_t)(ks * 8 + rh * 4 + p) * B_ + b2)
                = make_ulonglong2(aA[p], aB[p]);
        }
    }
}

// Gates, 4-slice reduce: 256 threads, it = (pair-half p, unit j2, batch b).
__device__ __forceinline__ void gates4(const uint64_t* __restrict__ gpl,
                                       float* __restrict__ cst,
                                       const float* __restrict__ bb,
                                       int it, int t, int j0,
                                       float* __restrict__ hout, int cbase) {
    int p  = it >> 7;
    int j2 = (it >> 6) & 1;
    int b  = it & 63;
    const float* gf = (const float*)gpl;
    float sg[4];
#pragma unroll
    for (int g = 0; g < 4; ++g) {
        int pi = g * 2 + p;
        float v = gf[((size_t)pi * B_ + b) * 2 + j2];
#pragma unroll
        for (int ss = 1; ss < 4; ++ss)
            v += gf[(((size_t)ss * 8 + pi) * B_ + b) * 2 + j2];
        sg[g] = v;
    }
    int j = 2 * p + j2;
    float gi  = sg[0] + bb[j];
    float gfv = sg[1] + bb[4 + j];
    float gg  = sg[2] + bb[8 + j];
    float go  = sg[3] + bb[12 + j];
    float si = fast_sigmoid(gi);
    float sf = fast_sigmoid(gfv);
    float so = fast_sigmoid(go);
    float tg = fast_tanh(gg);
    int ci = cbase + j * 64 + b;
    float c = sf * cst[ci] + si * tg;
    cst[ci] = c;
    hout[(size_t)t * H_ * B_ + (size_t)(j0 + j) * B_ + b] = so * fast_tanh(c);
}

// prep: zero counters + transpose x[b][t][k] -> g_xT[t][k][b]
__global__ void prep_kernel(const float* __restrict__ x) {
    __shared__ float tile[64][65];
    int t = blockIdx.x;
    if (threadIdx.x == 0) {
        g_cntA[t] = 0;
        g_cntB[t] = 0;
        if (t == 0) { g_cntA[T_] = 0; g_cntB[T_] = 0; }
    }
    for (int i = threadIdx.x; i < 64 * 64; i += blockDim.x) {
        int b = i >> 6, k = i & 63;
        tile[b][k] = x[(size_t)b * T_ * D_ + (size_t)t * D_ + k];
    }
    __syncthreads();
    for (int i = threadIdx.x; i < 64 * 64; i += blockDim.x) {
        int k = i >> 6, b = i & 63;
        g_xT[(size_t)t * D_ * B_ + (size_t)k * B_ + b] = tile[b][k];
    }
}

__global__ __launch_bounds__(NTHR, 1)
void lstm_kernel(const float* __restrict__ Wih0, const float* __restrict__ Whh0,
                 const float* __restrict__ bih0, const float* __restrict__ bhh0,
                 const float* __restrict__ Wih1, const float* __restrict__ Whh1,
                 const float* __restrict__ bih1, const float* __restrict__ bhh1,
                 const float* __restrict__ Wlin, const float* __restrict__ blin,
                 float* __restrict__ out) {
    extern __shared__ unsigned char smem[];
    float*    w0   = (float*)(smem + OFF_W0);      // [K0][16]
    float*    w1   = (float*)(smem + OFF_W1);      // [K1][16]
    uint64_t* gp0  = (uint64_t*)(smem + OFF_GP0);  // [2 buf][4 sl][8 p][64 b]
    uint64_t* gp1  = (uint64_t*)(smem + OFF_GP1);  // [2 buf][4 sl][8 p][64 b]
    float*    cst  = (float*)(smem + OFF_CST);     // [2][4][64]
    float*    bias = (float*)(smem + OFF_BIA);     // [2][16]

    const int tid  = threadIdx.x;
    const int lane = tid & 31;
    const int w    = tid >> 5;                     // warp 0..15
    const int ks   = w & 3;                        // k-slice 0..3 (128k each)
    const int rh   = (w >> 2) & 1;                 // row-half: pairs 4rh..+3
    const int bh   = w >> 3;                       // batch half
    const int h    = lane >> 4;                    // k-parity
    const int m    = lane & 15;
    const int b2   = bh * 32 + 2 * m;              // batches b2, b2+1
    const int pq   = 2 * rh;                       // ulonglong2 base index
    const int j0   = blockIdx.x * 4;

    const int kb  = ks * 128, ke = kb + 128;       // recurrent k-slice
    const int xkb = ks * 16,  xke = xkb + 16;      // x-ff k-slice

    // ---- load weights (row r = gate*4 + j; k<H_ -> W_hh else W_ih) ----
    for (int idx = tid; idx < K0 * ROWS; idx += NTHR) {
        int k = idx >> 4, rr = idx & 15;
        int row = (rr >> 2) * H_ + j0 + (rr & 3);
        w0[idx] = (k < H_) ? Whh0[(size_t)row * H_ + k]
                           : Wih0[(size_t)row * D_ + (k - H_)];
    }
    for (int idx = tid; idx < K1 * ROWS; idx += NTHR) {
        int k = idx >> 4, rr = idx & 15;
        int row = (rr >> 2) * H_ + j0 + (rr & 3);
        w1[idx] = (k < H_) ? Whh1[(size_t)row * H_ + k]
                           : Wih1[(size_t)row * H_ + (k - H_)];
    }
    if (tid < 32) {
        int l = tid >> 4, rr = tid & 15;
        int row = (rr >> 2) * H_ + j0 + (rr & 3);
        bias[tid] = l ? (bih1[row] + bhh1[row]) : (bih0[row] + bhh0[row]);
    }
    cst[tid] = 0.f;                                // exactly 512 entries
    __syncthreads();

    const float* w0x  = w0 + (size_t)H_ * ROWS;    // layer0 x-ff rows
    const float* w1ff = w1 + (size_t)H_ * ROWS;    // layer1 h1-ff rows

#pragma unroll 1
    for (int r = 0; r <= T_ + 1; ++r) {
        // ===== gates (both layers, all warps), reading LAST round's gp ====
        if (tid < 256) {
            if (r >= 2)
                gates4(gp1 + (size_t)((r - 1) & 1) * GPW, cst, bias + 16,
                       tid, r - 2, j0, g_h2, 256);
            __threadfence();
            asm volatile("bar.sync 3, 256;" ::: "memory");
            if (tid == 0 && r >= 2) atomicAdd(&g_cntB[r - 2], 1);
        } else {
            if (r >= 1 && r <= T_)
                gates4(gp0 + (size_t)((r - 1) & 1) * GPW, cst, bias,
                       tid - 256, r - 1, j0, g_h1, 0);
            __threadfence();
            asm volatile("bar.sync 4, 256;" ::: "memory");
            if (tid == 256 && r >= 1 && r <= T_) atomicAdd(&g_cntA[r - 1], 1);
        }

        // ===== gemv: rec-L1, fused h1 (L1-ff + L0-rec), x-ff ==============
        uint64_t a1A[4], a1B[4], a0A[4], a0B[4];
#pragma unroll
        for (int i = 0; i < 4; ++i) {
            a1A[i] = 0ull; a1B[i] = 0ull; a0A[i] = 0ull; a0B[i] = 0ull;
        }
        if (r >= 2 && r <= T_) {
            wait_warp(&g_cntB[r - 2]);
            gemv4p(a1A, a1B, w1, g_h2 + (size_t)(r - 2) * H_ * B_,
                   kb, ke, b2, h, pq);
        }
        if (r >= 1 && r <= T_) {
            wait_warp(&g_cntA[r - 1]);
            gemv4p_pair(a1A, a1B, a0A, a0B, w1ff, w0,
                        g_h1 + (size_t)(r - 1) * H_ * B_,
                        kb, ke, b2, h, pq);
        }
        if (r < T_)
            gemv4p(a0A, a0B, w0x, g_xT + (size_t)r * D_ * B_,
                   xkb, xke, b2, h, pq);

        cstore4(a1A, a1B, gp1 + (size_t)(r & 1) * GPW, ks, rh, b2, lane);
        cstore4(a0A, a0B, gp0 + (size_t)(r & 1) * GPW, ks, rh, b2, lane);
        __syncthreads();                           // one sync per round
    }

    // ---- head on CTA 0: logits = h2[:,T-1] @ Wlin^T + blin; log_softmax ----
    if (blockIdx.x == 0) {
        if (tid == 0) {
            while (ld_acq(&g_cntB[T_ - 1]) < NCTA) {}
        }
        __syncthreads();
        float* hv = (float*)smem;                      // [64][521]
        float* lg = (float*)(smem + OFF_LG);           // [640]
        const float* h2l = g_h2 + (size_t)(T_ - 1) * H_ * B_;
        for (int idx = tid; idx < H_ * B_; idx += NTHR) {
            int k = idx >> 6, b = idx & 63;
            hv[b * HV_STRIDE + k] = h2l[idx];
        }
        __syncthreads();
        for (int pr = w * 40; pr < w * 40 + 40; ++pr) {
            int b = pr / OUT_, o = pr % OUT_;
            float sum = 0.f;
            for (int i = lane; i < H_; i += 32)
                sum += hv[b * HV_STRIDE + i] * Wlin[(size_t)o * H_ + i];
#pragma unroll
            for (int off = 16; off; off >>= 1)
                sum += __shfl_xor_sync(0xffffffffu, sum, off);
            if (lane == 0) lg[pr] = sum + blin[o];
        }
        __syncthreads();
        if (tid < B_) {
            float mx = -1e30f;
#pragma unroll
            for (int q = 0; q < OUT_; ++q) mx = fmaxf(mx, lg[tid * OUT_ + q]);
            float z = 0.f;
#pragma unroll
            for (int q = 0; q < OUT_; ++q) z += expf(lg[tid * OUT_ + q] - mx);
            float lse = mx + logf(z);
#pragma unroll
            for (int q = 0; q < OUT_; ++q)
                out[tid * OUT_ + q] = lg[tid * OUT_ + q] - lse;
        }
    }
}

extern "C" void kernel_launch(void* const* d_in, const int* in_sizes, int n_in,
                              void* d_out, int out_size) {
    const float* x    = (const float*)d_in[0];
    const float* Wih0 = (const float*)d_in[1];
    const float* Whh0 = (const float*)d_in[2];
    const float* bih0 = (const float*)d_in[3];
    const float* bhh0 = (const float*)d_in[4];
    const float* Wih1 = (const float*)d_in[5];
    const float* Whh1 = (const float*)d_in[6];
    const float* bih1 = (const float*)d_in[7];
    const float* bhh1 = (const float*)d_in[8];
    const float* Wlin = (const float*)d_in[9];
    const float* blin = (const float*)d_in[10];
    float* out = (float*)d_out;

    cudaFuncSetAttribute(lstm_kernel,
                         cudaFuncAttributeMaxDynamicSharedMemorySize,
                         (int)SMEM_BYTES);

    prep_kernel<<<T_, 256>>>(x);
    lstm_kernel<<<NCTA, NTHR, SMEM_BYTES>>>(Wih0, Whh0, bih0, bhh0,
                                            Wih1, Whh1, bih1, bhh1,
                                            Wlin, blin, out);
}